// round 11
// baseline (speedup 1.0000x reference)
#include <cuda_runtime.h>
#include <math.h>

#define PATCH    32
#define HP       256
#define WP       256
#define NPATCH   (HP * WP)        // 65536
#define IMG_W    8192
#define NGRID    (NPATCH / 4)     // 16384 CTAs, 4 patches each
#define GROUPS   64               // 64 groups x 256 CTAs
#define GSIZE    256

// ln(0.04 * sqrt(2*pi)) = -2.2999372...
#define LOG_NORM_CONST (-2.2999372199f)

// Level-1 per-CTA partials, level-2 per-group partials, arrival counters.
__device__ float4 g_part1[NGRID];
__device__ float4 g_part2[GROUPS];
__device__ unsigned int g_cnt1[GROUPS];   // zero-init; reset after use
__device__ unsigned int g_cnt2;           // zero-init; reset after use

// One CTA per group of 4 horizontally adjacent patches (round-2/3 memory
// shape: MLP_p1=4, 14 waves of small CTAs -> minimal completion spread).
// Tail: fused mask/terms -> one float4 partial; hierarchical last-CTA finish.
__global__ void __launch_bounds__(256, 8)
fused_kernel(const float* __restrict__ x, const float* __restrict__ tmask,
             float* __restrict__ out) {
    const int g   = blockIdx.x;          // CTA index
    const int ph  = g >> 6;              // patch row (64 CTA-groups per row)
    const int pg  = g & 63;              // group col
    const int tid = threadIdx.x;
    const int row = tid >> 3;            // 0..31
    const int q   = tid & 7;             // 0..7

    const size_t base = (size_t)(ph * PATCH + row) * IMG_W + (size_t)pg * 128;
    const float4* p4 = (const float4*)(x + base);

    float s[4];
    #pragma unroll
    for (int k = 0; k < 4; k++) {        // 4 independent loads (MLP 4)
        const float4 v = __ldcs(p4 + k * 8 + q);
        s[k] = (v.x + v.y) + (v.z + v.w);
    }

    // Full-warp xor reduce each of the 4 partials.
    #pragma unroll
    for (int o = 16; o > 0; o >>= 1) {
        #pragma unroll
        for (int k = 0; k < 4; k++)
            s[k] += __shfl_xor_sync(0xffffffffu, s[k], o);
    }

    __shared__ float sm[8][4];
    const int w = tid >> 5;
    const int l = tid & 31;
    if (l == 0) {
        #pragma unroll
        for (int k = 0; k < 4; k++) sm[w][k] = s[k];
    }
    __syncthreads();

    if (tid < 32) {
        // lane = warp*4 + k layout; reduce across the 8 warps.
        float v = sm[tid >> 2][tid & 3];
        v += __shfl_xor_sync(0xffffffffu, v, 4);
        v += __shfl_xor_sync(0xffffffffu, v, 8);
        v += __shfl_xor_sync(0xffffffffu, v, 16);

        float ps = 0.0f, ns = 0.0f, pc = 0.0f;
        if (tid < 4) {
            const float mean = v * (1.0f / (PATCH * PATCH));
            const float z = (mean - 0.34f) * 25.0f;
            const float logpdf = -0.5f * z * z - LOG_NORM_CONST;
            const float pos_t = -logf(expf(logpdf) + 1e-6f);
            const float neg_t = mean * mean;
            const float mk = (tmask[ph * WP + pg * 4 + tid] >= 0.5f) ? 1.0f : 0.0f;
            ps = pos_t * mk;
            ns = neg_t * (1.0f - mk);
            pc = mk;
        }
        #pragma unroll
        for (int o = 2; o > 0; o >>= 1) {
            ps += __shfl_xor_sync(0xffffffffu, ps, o);
            ns += __shfl_xor_sync(0xffffffffu, ns, o);
            pc += __shfl_xor_sync(0xffffffffu, pc, o);
        }
        if (tid == 0)
            g_part1[g] = make_float4(ps, ns, pc, 0.0f);
    }

    // ---- Level-1 arrival: last CTA of each 256-CTA group reduces it ----
    const int gid = g >> 8;
    __shared__ bool s_glast;
    if (tid == 0) {
        __threadfence();
        const unsigned int old = atomicAdd(&g_cnt1[gid], 1u);
        s_glast = (old == GSIZE - 1);
        if (s_glast) g_cnt1[gid] = 0;     // reset for next replay
    }
    __syncthreads();
    if (!s_glast) return;
    __threadfence();

    // Reduce this group's 256 partials in fixed order (one per thread).
    {
        const float4 p = g_part1[gid * GSIZE + tid];
        float ps = p.x, ns = p.y, pc = p.z;
        #pragma unroll
        for (int o = 16; o > 0; o >>= 1) {
            ps += __shfl_xor_sync(0xffffffffu, ps, o);
            ns += __shfl_xor_sync(0xffffffffu, ns, o);
            pc += __shfl_xor_sync(0xffffffffu, pc, o);
        }
        __shared__ float3 pr[8];
        if (l == 0) pr[w] = make_float3(ps, ns, pc);
        __syncthreads();
        if (tid < 8) {
            float3 a = pr[tid];
            float cps = a.x, cns = a.y, cpc = a.z;
            #pragma unroll
            for (int o = 4; o > 0; o >>= 1) {
                cps += __shfl_xor_sync(0xffu, cps, o);
                cns += __shfl_xor_sync(0xffu, cns, o);
                cpc += __shfl_xor_sync(0xffu, cpc, o);
            }
            if (tid == 0)
                g_part2[gid] = make_float4(cps, cns, cpc, 0.0f);
        }
    }

    // ---- Level-2 arrival: globally last group writes the scalar ----
    __shared__ bool s_final;
    if (tid == 0) {
        __threadfence();
        const unsigned int old = atomicAdd(&g_cnt2, 1u);
        s_final = (old == GROUPS - 1);
        if (s_final) g_cnt2 = 0;          // reset for next replay
    }
    __syncthreads();
    if (!s_final) return;
    __threadfence();

    if (tid < 64) {
        const float4 p = g_part2[tid];
        float ps = p.x, ns = p.y, pc = p.z;
        #pragma unroll
        for (int o = 16; o > 0; o >>= 1) {
            ps += __shfl_xor_sync(0xffffffffu, ps, o);
            ns += __shfl_xor_sync(0xffffffffu, ns, o);
            pc += __shfl_xor_sync(0xffffffffu, pc, o);
        }
        __shared__ float3 fr[2];
        if (l == 0) fr[w] = make_float3(ps, ns, pc);
        __syncwarp();
        if (tid == 0) {
            // combine the two warps' results in fixed order
            // (warp 1's value written by tid 32)
        }
    }
    __syncthreads();
    {
        __shared__ float3 fr2[2];
        if (tid < 64) {
            const float4 p = g_part2[tid];
            float ps = p.x, ns = p.y, pc = p.z;
            #pragma unroll
            for (int o = 16; o > 0; o >>= 1) {
                ps += __shfl_xor_sync(0xffffffffu, ps, o);
                ns += __shfl_xor_sync(0xffffffffu, ns, o);
                pc += __shfl_xor_sync(0xffffffffu, pc, o);
            }
            if (l == 0) fr2[w] = make_float3(ps, ns, pc);
        }
        __syncthreads();
        if (tid == 0) {
            const float fps = fr2[0].x + fr2[1].x;
            const float fns = fr2[0].y + fr2[1].y;
            const float fpc = fr2[0].z + fr2[1].z;
            const float fnc = (float)NPATCH - fpc;
            out[0] = fps / fpc + fns / fnc;
        }
    }
}

extern "C" void kernel_launch(void* const* d_in, const int* in_sizes, int n_in,
                              void* d_out, int out_size) {
    const float* unet  = (const float*)d_in[0];   // [1,1,8192,8192] fp32
    const float* tmask = (const float*)d_in[1];   // [1,256,256] fp32
    float* out = (float*)d_out;

    fused_kernel<<<NGRID, 256>>>(unet, tmask, out);
}

// round 12
// speedup vs baseline: 1.1117x; 1.1117x over previous
#include <cuda_runtime.h>
#include <math.h>

#define PATCH    32
#define HP       256
#define WP       256
#define NPATCH   (HP * WP)        // 65536
#define IMG_W    8192
#define IMG_W4   (IMG_W / 4)      // 2048 float4 per row
#define PPB      64               // patches per CTA (8 warps x 8 iters)
#define NGRID1   (NPATCH / PPB)   // 1024 CTAs

// ln(0.04 * sqrt(2*pi)) = -2.2999372...
#define LOG_NORM_CONST (-2.2999372199f)

// Per-CTA partials: (pos_sum, neg_sum, pos_count, unused)
__device__ float4 g_part[NGRID1];
__device__ unsigned int g_count;   // zero-initialized; reset by last CTA

// Round-5 structure (best measured), with PLAIN global loads instead of
// __ldcs: both >6.4TB/s runs this session used default caching policy;
// every __ldcs variant capped at <=6.28TB/s.
__global__ void __launch_bounds__(256, 8)
fused_kernel(const float* __restrict__ x, const float* __restrict__ tmask,
             float* __restrict__ out) {
    const int tid = threadIdx.x;
    const int w   = tid >> 5;            // warp 0..7
    const int l   = tid & 31;            // lane
    const int p_base = blockIdx.x * PPB; // first patch of this CTA

    __shared__ float means[PPB];

    const int lrow = l >> 3;             // 0..3 base row
    const int lq   = l & 7;              // float4 within 128B row segment

    #pragma unroll
    for (int t = 0; t < 8; t++) {
        const int p  = p_base + t * 8 + w;
        const int ph = p >> 8;
        const int pw = p & 255;
        const float4* p4 = (const float4*)x
                         + (size_t)(ph * PATCH) * IMG_W4 + (size_t)pw * 8;

        float s = 0.0f;
        #pragma unroll
        for (int k = 0; k < 8; k++) {    // 8 independent loads in flight
            const float4 v = p4[(size_t)(lrow + 4 * k) * IMG_W4 + lq];
            s += (v.x + v.y) + (v.z + v.w);
        }

        #pragma unroll
        for (int o = 16; o > 0; o >>= 1)
            s += __shfl_xor_sync(0xffffffffu, s, o);

        if (l == 0) means[t * 8 + w] = s * (1.0f / (PATCH * PATCH));
    }
    __syncthreads();

    // Tail: 64 parallel term computations, then block reduce.
    float ps = 0.0f, ns = 0.0f, pc = 0.0f;
    if (tid < PPB) {
        const float mean = means[tid];
        const float z = (mean - 0.34f) * 25.0f;
        const float logpdf = -0.5f * z * z - LOG_NORM_CONST;
        const float pos_t = -logf(expf(logpdf) + 1e-6f);
        const float neg_t = mean * mean;
        const float mk = (tmask[p_base + tid] >= 0.5f) ? 1.0f : 0.0f;
        ps = pos_t * mk;
        ns = neg_t * (1.0f - mk);
        pc = mk;
    }

    if (tid < 64) {
        #pragma unroll
        for (int o = 16; o > 0; o >>= 1) {
            ps += __shfl_xor_sync(0xffffffffu, ps, o);
            ns += __shfl_xor_sync(0xffffffffu, ns, o);
            pc += __shfl_xor_sync(0xffffffffu, pc, o);
        }
    }
    __shared__ float3 pr[2];
    if (tid == 0 || tid == 32) pr[tid >> 5] = make_float3(ps, ns, pc);
    __syncthreads();

    __shared__ bool s_last;
    if (tid == 0) {
        const float3 a = pr[0], b = pr[1];
        g_part[blockIdx.x] = make_float4(a.x + b.x, a.y + b.y, a.z + b.z, 0.0f);
        __threadfence();
        const unsigned int old = atomicAdd(&g_count, 1u);
        s_last = (old == NGRID1 - 1);
    }
    __syncthreads();

    if (!s_last) return;

    // ---- Last CTA: reduce all 1024 partials in fixed order (deterministic) ----
    float fps = 0.0f, fns = 0.0f, fpc = 0.0f;
    #pragma unroll
    for (int k = 0; k < NGRID1 / 256; k++) {      // 4 independent loads
        const float4 p = g_part[tid + k * 256];
        fps += p.x; fns += p.y; fpc += p.z;
    }

    #pragma unroll
    for (int o = 16; o > 0; o >>= 1) {
        fps += __shfl_xor_sync(0xffffffffu, fps, o);
        fns += __shfl_xor_sync(0xffffffffu, fns, o);
        fpc += __shfl_xor_sync(0xffffffffu, fpc, o);
    }

    __shared__ float f_ps[8], f_ns[8], f_pc[8];
    if (l == 0) { f_ps[w] = fps; f_ns[w] = fns; f_pc[w] = fpc; }
    __syncthreads();

    if (tid < 8) {
        fps = f_ps[tid]; fns = f_ns[tid]; fpc = f_pc[tid];
        #pragma unroll
        for (int o = 4; o > 0; o >>= 1) {
            fps += __shfl_xor_sync(0xffu, fps, o);
            fns += __shfl_xor_sync(0xffu, fns, o);
            fpc += __shfl_xor_sync(0xffu, fpc, o);
        }
        if (tid == 0) {
            const float fnc = (float)NPATCH - fpc;
            out[0] = fps / fpc + fns / fnc;
            g_count = 0;                  // reset for next graph replay
        }
    }
}

extern "C" void kernel_launch(void* const* d_in, const int* in_sizes, int n_in,
                              void* d_out, int out_size) {
    const float* unet  = (const float*)d_in[0];   // [1,1,8192,8192] fp32
    const float* tmask = (const float*)d_in[1];   // [1,256,256] fp32
    float* out = (float*)d_out;

    fused_kernel<<<NGRID1, 256>>>(unet, tmask, out);
}